// round 8
// baseline (speedup 1.0000x reference)
#include <cuda_runtime.h>
#include <cstdint>
#include <cstddef>

// ---------------------------------------------------------------------------
// Problem constants
// ---------------------------------------------------------------------------
#define B_SZ   8192
#define D_SZ   8
#define P_SZ   10
#define R_SZ   512
#define OUT_SZ 64
#define NMID   6
#define KTOT   (P_SZ * R_SZ)   // 5120
#define KC     64              // K per pipeline chunk (64B int8 rows)
#define NCHI   (KTOT / KC)     // 80 chunks
#define RCHI   (R_SZ / KC)     // 8 chunks per j-group

// ---------------------------------------------------------------------------
// Device-global scratch
// ---------------------------------------------------------------------------
__device__ float  g_tanh_g0[P_SZ * R_SZ];
__device__ float  g_resf[(size_t)B_SZ * R_SZ];                 // f32 res (master out)
__device__ int8_t g_qa_hi[(size_t)B_SZ * R_SZ];                // quantized res hi
__device__ int8_t g_qa_lo[(size_t)B_SZ * R_SZ];                // quantized res lo
__device__ float  g_sa[B_SZ];                                  // per-row scale of res
// B operands, [layer][n][k], int8 split
__device__ int8_t g_qb_hi_mid[(size_t)NMID * R_SZ * KTOT];
__device__ int8_t g_qb_lo_mid[(size_t)NMID * R_SZ * KTOT];
__device__ int8_t g_qb_hi_last[(size_t)OUT_SZ * KTOT];
__device__ int8_t g_qb_lo_last[(size_t)OUT_SZ * KTOT];
__device__ float  g_sb_mid[NMID * P_SZ * R_SZ];                // per (layer,j,n)
__device__ float  g_sb_last[P_SZ * OUT_SZ];
__device__ float  g_sbmax_mid[NMID * P_SZ * R_SZ];
__device__ float  g_sbmax_last[P_SZ * OUT_SZ];
__device__ float  g_bstage_mid[(size_t)NMID * R_SZ * KTOT];    // f32 transposed tanh(G)
__device__ float  g_bstage_last[(size_t)OUT_SZ * KTOT];

// ---------------------------------------------------------------------------
// PTX helpers (sm_80-era: cp.async, ldmatrix, mma.sync — NO tcgen05)
// ---------------------------------------------------------------------------
__device__ __forceinline__ uint32_t smem_u32(const void* p) {
    uint32_t a;
    asm("{ .reg .u64 t; cvta.to.shared.u64 t, %1; cvt.u32.u64 %0, t; }" : "=r"(a) : "l"(p));
    return a;
}
#define CP_ASYNC16(dst, src) \
    asm volatile("cp.async.cg.shared.global [%0], [%1], 16;" :: "r"(dst), "l"(src) : "memory")
#define CP_COMMIT() asm volatile("cp.async.commit_group;" ::: "memory")
#define CP_WAIT2()  asm volatile("cp.async.wait_group 2;" ::: "memory")

#define LDSM4(r0, r1, r2, r3, addr) \
    asm volatile("ldmatrix.sync.aligned.m8n8.x4.shared.b16 {%0,%1,%2,%3}, [%4];" \
                 : "=r"(r0), "=r"(r1), "=r"(r2), "=r"(r3) : "r"(addr))

// int8 MMA m16n8k32, s32 accumulate
#define MMA_S8(d, a, b) \
    asm volatile("mma.sync.aligned.m16n8k32.row.col.s32.s8.s8.s32 " \
                 "{%0,%1,%2,%3}, {%4,%5,%6,%7}, {%8,%9}, {%0,%1,%2,%3};" \
                 : "+r"((d)[0]), "+r"((d)[1]), "+r"((d)[2]), "+r"((d)[3]) \
                 : "r"((a)[0]), "r"((a)[1]), "r"((a)[2]), "r"((a)[3]), \
                   "r"((b)[0]), "r"((b)[1]))

// 64B-row XOR swizzle (proven conflict-free across ldmatrix 8-row phases)
__device__ __forceinline__ uint32_t sw64(uint32_t row, uint32_t c16) {
    return row * 64u + ((c16 ^ ((row >> 1) & 3u)) << 4);
}

__device__ __forceinline__ int clamp127(int v) {
    return v < -127 ? -127 : (v > 127 ? 127 : v);
}

// ---------------------------------------------------------------------------
// Precompute kernels
// ---------------------------------------------------------------------------
__global__ void tanh_small_kernel(const float* __restrict__ src,
                                  float* __restrict__ dst, int n) {
    int i = blockIdx.x * blockDim.x + threadIdx.x;
    if (i < n) dst[i] = tanhf(src[i]);
}

__global__ void zero_scales_kernel() {
    int i = blockIdx.x * blockDim.x + threadIdx.x;
    if (i < NMID * P_SZ * R_SZ) g_sbmax_mid[i] = 0.f;
    if (i < P_SZ * OUT_SZ)      g_sbmax_last[i] = 0.f;
}

// pass1: tanh + transpose G [R,P,N] -> staging f32 [n][j*512+r]; atomicMax |.|
__global__ void btrans_pass1_kernel(const float* __restrict__ G,
                                    float* __restrict__ stage,
                                    float* __restrict__ sbmax,
                                    int N, size_t gStride, size_t stStride) {
    __shared__ float t[32][33];
    int layer = blockIdx.z / P_SZ;
    int j     = blockIdx.z % P_SZ;
    const float* Gp = G + (size_t)layer * gStride;
    float* stp = stage + (size_t)layer * stStride;
    float* sbm = sbmax + (size_t)layer * P_SZ * N;
    int rt = blockIdx.x * 32, nt = blockIdx.y * 32;
    int tx = threadIdx.x, ty = threadIdx.y;   // (32, 8)
#pragma unroll
    for (int yy = ty; yy < 32; yy += 8)
        t[yy][tx] = tanhf(Gp[((size_t)(rt + yy) * P_SZ + j) * N + nt + tx]);
    __syncthreads();
#pragma unroll
    for (int yy = ty; yy < 32; yy += 8) {
        int n = nt + yy, r = rt + tx;
        float x = t[tx][yy];
        stp[(size_t)n * KTOT + (size_t)j * R_SZ + r] = x;
        float a = fabsf(x);
#pragma unroll
        for (int o = 16; o; o >>= 1) a = fmaxf(a, __shfl_xor_sync(0xffffffffu, a, o));
        if (tx == 0) atomicMax((int*)&sbm[j * N + n], __float_as_int(a));
    }
}

// pass2: staging -> int8 hi/lo + final scale array
__global__ void btrans_pass2_kernel(const float* __restrict__ stage,
                                    const float* __restrict__ sbmax,
                                    int8_t* __restrict__ qh, int8_t* __restrict__ ql,
                                    float* __restrict__ sb, int N, long total) {
    long idx = (long)blockIdx.x * blockDim.x + threadIdx.x;
    if (idx >= total) return;
    long perL = (long)N * KTOT;
    int layer = (int)(idx / perL);
    long rem  = idx % perL;
    int n = (int)(rem / KTOT);
    int k = (int)(rem % KTOT);
    int j = k >> 9;
    float mx = sbmax[(size_t)layer * P_SZ * N + j * N + n];
    float s  = fmaxf(mx, 1e-30f) * (1.0f / 127.0f);
    float qv = stage[idx] / s;
    int h = clamp127((int)rintf(qv));
    int l = clamp127((int)rintf((qv - (float)h) * 128.0f));
    qh[idx] = (int8_t)h;
    ql[idx] = (int8_t)l;
    if ((k & 511) == 0) sb[(size_t)layer * P_SZ * N + j * N + n] = s;
}

// First core -> f32 res
__global__ void first_core_kernel(const float* __restrict__ z,
                                  float* __restrict__ resf) {
    int b = blockIdx.x;
    int r = threadIdx.x;
    float zv = z[b * D_SZ + 0];
    float ph = 1.f, acc = 0.f;
#pragma unroll
    for (int j = 0; j < P_SZ; j++) {
        acc += g_tanh_g0[j * R_SZ + r] * ph;
        ph *= zv;
    }
    resf[(size_t)b * R_SZ + r] = acc;
}

// Quantize res rows: per-row absmax -> int8 hi/lo + scale
__global__ void quant_res_kernel(const float* __restrict__ resf,
                                 int8_t* __restrict__ qh, int8_t* __restrict__ ql,
                                 float* __restrict__ sa) {
    __shared__ float wmax[16];
    int b = blockIdx.x, tid = threadIdx.x;   // 512 threads
    float x = resf[(size_t)b * R_SZ + tid];
    float a = fabsf(x);
#pragma unroll
    for (int o = 16; o; o >>= 1) a = fmaxf(a, __shfl_xor_sync(0xffffffffu, a, o));
    if ((tid & 31) == 0) wmax[tid >> 5] = a;
    __syncthreads();
    if (tid < 32) {
        float m = (tid < 16) ? wmax[tid] : 0.f;
#pragma unroll
        for (int o = 8; o; o >>= 1) m = fmaxf(m, __shfl_xor_sync(0xffffffffu, m, o));
        if (tid == 0) wmax[0] = m;
    }
    __syncthreads();
    float s = fmaxf(wmax[0], 1e-30f) * (1.0f / 127.0f);
    float qv = x / s;
    int h = clamp127((int)rintf(qv));
    int l = clamp127((int)rintf((qv - (float)h) * 128.0f));
    qh[(size_t)b * R_SZ + tid] = (int8_t)h;
    ql[(size_t)b * R_SZ + tid] = (int8_t)l;
    if (tid == 0) sa[b] = s;
}

// ---------------------------------------------------------------------------
// int8 IMMA 3-pass GEMM with Horner phi folding.
//   per j (desc): Cint += Ah.Bh (C1), Ah.Bl + Al.Bh (C2) over 8 chunks of k64;
//   at group end: master = master*z + sA*sB*(C1 + C2/128)
// BM=128, BN=64, 512 threads, warp grid 4x4, warp tile 32x16 (MT=2, NT=2).
// 4-stage cp.async pipeline. Epilogue writes f32.
// ---------------------------------------------------------------------------
__global__ void __launch_bounds__(512, 1)
tt_imma_kernel(const int8_t* __restrict__ Ahi, const int8_t* __restrict__ Alo,
               const int8_t* __restrict__ Bhi, const int8_t* __restrict__ Blo,
               const float* __restrict__ sa, const float* __restrict__ sb,
               const float* __restrict__ z, int zcol,
               float* __restrict__ outp, int Ntot) {
    constexpr int BM = 128, BN = 64;
    constexpr int A_T = BM * 64;          // 8KB per A array per stage
    constexpr int B_T = BN * 64;          // 4KB
    constexpr int STAGE = 2 * A_T + 2 * B_T;   // 24KB

    extern __shared__ __align__(16) char sm[];
    const uint32_t base = smem_u32(sm);

    const int tid = threadIdx.x, lane = tid & 31, wid = tid >> 5;
    const int m0 = blockIdx.y * BM, n0 = blockIdx.x * BN;
    const int wm0 = (wid >> 2) * 32;      // 4 M warp-rows
    const int wn0 = (wid & 3) * 16;       // 4 N warp-cols

    // per-lane constants
    const int rowA0 = m0 + wm0 + (lane >> 2);       // mt adds 16
    float zA[2], zB[2], saA[2], saB[2];
#pragma unroll
    for (int mt = 0; mt < 2; mt++) {
        int rA = rowA0 + mt * 16;
        zA[mt] = z[(size_t)rA * D_SZ + zcol];
        zB[mt] = z[(size_t)(rA + 8) * D_SZ + zcol];
        saA[mt] = sa[rA];
        saB[mt] = sa[rA + 8];
    }
    const int colB0 = n0 + wn0 + (lane & 3) * 2;    // nt adds 8

    float M[2][2][4];
    int   C1[2][2][4], C2[2][2][4];
#pragma unroll
    for (int mt = 0; mt < 2; mt++)
#pragma unroll
        for (int nt = 0; nt < 2; nt++)
#pragma unroll
            for (int q = 0; q < 4; q++) { M[mt][nt][q] = 0.f; C1[mt][nt][q] = 0; C2[mt][nt][q] = 0; }

    auto produce = [&](int cc) {
        const int s = cc & 3;
        const int j = (P_SZ - 1) - (cc >> 3);
        const int rr = cc & (RCHI - 1);
        const int roffA = rr * KC;
        const int koffB = j * R_SZ + rr * KC;
        const uint32_t aH = base + s * STAGE;
        const uint32_t aL = aH + A_T;
        const uint32_t bH = aH + 2 * A_T;
        const uint32_t bL = bH + B_T;
        {   // A: 128 rows x 4 c16 = 512 transfers per array; 1 per thread per array
            const int row = tid >> 2, c16 = tid & 3;
            const uint32_t off = sw64(row, c16);
            const size_t go = (size_t)(m0 + row) * R_SZ + roffA + c16 * 16;
            CP_ASYNC16(aH + off, Ahi + go);
            CP_ASYNC16(aL + off, Alo + go);
        }
        if (tid < 256) {   // B: 64 rows x 4 c16 = 256 per array
            const int row = tid >> 2, c16 = tid & 3;
            const uint32_t off = sw64(row, c16);
            const size_t go = (size_t)(n0 + row) * KTOT + koffB + c16 * 16;
            CP_ASYNC16(bH + off, Bhi + go);
            CP_ASYNC16(bL + off, Blo + go);
        }
        CP_COMMIT();
    };

    auto mma_chunk = [&](int s) {
        const uint32_t aH = base + s * STAGE;
        const uint32_t aL = aH + A_T;
        const uint32_t bH = aH + 2 * A_T;
        const uint32_t bL = bH + B_T;
        const uint32_t rowa = wm0 + (lane & 15);
        const uint32_t rowb = wn0 + ((lane >> 4) << 3) + (lane & 7);
#pragma unroll
        for (int ks = 0; ks < 2; ks++) {
            const uint32_t c16a = (lane >> 4) + 2 * ks;
            const uint32_t c16b = ((lane >> 3) & 1) + 2 * ks;
            const uint32_t aoff = sw64(rowa, c16a);        // +1024 for mt=1
            const uint32_t boff = sw64(rowb, c16b);
            uint32_t ah0[4], ah1[4], al0[4], al1[4], bh[4], bl[4];
            LDSM4(bh[0], bh[1], bh[2], bh[3], bH + boff);
            LDSM4(bl[0], bl[1], bl[2], bl[3], bL + boff);
            LDSM4(ah0[0], ah0[1], ah0[2], ah0[3], aH + aoff);
            LDSM4(ah1[0], ah1[1], ah1[2], ah1[3], aH + aoff + 1024);
            // pass1: C1 += Ah*Bh
            MMA_S8(C1[0][0], ah0, bh + 0); MMA_S8(C1[0][1], ah0, bh + 2);
            MMA_S8(C1[1][0], ah1, bh + 0); MMA_S8(C1[1][1], ah1, bh + 2);
            // pass2: C2 += Ah*Bl
            MMA_S8(C2[0][0], ah0, bl + 0); MMA_S8(C2[0][1], ah0, bl + 2);
            MMA_S8(C2[1][0], ah1, bl + 0); MMA_S8(C2[1][1], ah1, bl + 2);
            LDSM4(al0[0], al0[1], al0[2], al0[3], aL + aoff);
            LDSM4(al1[0], al1[1], al1[2], al1[3], aL + aoff + 1024);
            // pass3: C2 += Al*Bh
            MMA_S8(C2[0][0], al0, bh + 0); MMA_S8(C2[0][1], al0, bh + 2);
            MMA_S8(C2[1][0], al1, bh + 0); MMA_S8(C2[1][1], al1, bh + 2);
        }
    };

    auto convert = [&](int jprev) {
        const float* sbj = sb + jprev * Ntot;
#pragma unroll
        for (int nt = 0; nt < 2; nt++) {
            const int col = colB0 + nt * 8;
            float sb0 = sbj[col], sb1 = sbj[col + 1];
#pragma unroll
            for (int mt = 0; mt < 2; mt++) {
                float sc0 = saA[mt] * sb0, sc1 = saA[mt] * sb1;
                float sc2 = saB[mt] * sb0, sc3 = saB[mt] * sb1;
                float v0 = fmaf((float)C2[mt][nt][0], 0.0078125f, (float)C1[mt][nt][0]);
                float v1 = fmaf((float)C2[mt][nt][1], 0.0078125f, (float)C1[mt][nt][1]);
                float v2 = fmaf((float)C2[mt][nt][2], 0.0078125f, (float)C1[mt][nt][2]);
                float v3 = fmaf((float)C2[mt][nt][3], 0.0078125f, (float)C1[mt][nt][3]);
                M[mt][nt][0] = fmaf(M[mt][nt][0], zA[mt], v0 * sc0);
                M[mt][nt][1] = fmaf(M[mt][nt][1], zA[mt], v1 * sc1);
                M[mt][nt][2] = fmaf(M[mt][nt][2], zB[mt], v2 * sc2);
                M[mt][nt][3] = fmaf(M[mt][nt][3], zB[mt], v3 * sc3);
#pragma unroll
                for (int q = 0; q < 4; q++) { C1[mt][nt][q] = 0; C2[mt][nt][q] = 0; }
            }
        }
    };

    produce(0); produce(1); produce(2);

    for (int c = 0; c < NCHI; c++) {
        CP_WAIT2();
        __syncthreads();
        if (c + 3 < NCHI) produce(c + 3); else CP_COMMIT();
        if (c && (c & (RCHI - 1)) == 0) convert(P_SZ - (c >> 3));
        mma_chunk(c & 3);
    }
    convert(0);

    // epilogue: f32 master -> global
#pragma unroll
    for (int mt = 0; mt < 2; mt++) {
        const int row0 = rowA0 + mt * 16;
#pragma unroll
        for (int nt = 0; nt < 2; nt++) {
            const int col = colB0 + nt * 8;
            *reinterpret_cast<float2*>(&outp[(size_t)row0 * Ntot + col]) =
                make_float2(M[mt][nt][0], M[mt][nt][1]);
            *reinterpret_cast<float2*>(&outp[(size_t)(row0 + 8) * Ntot + col]) =
                make_float2(M[mt][nt][2], M[mt][nt][3]);
        }
    }
}

// ---------------------------------------------------------------------------
// Launch (graph-capturable, allocation-free)
// Inputs: z [B,D] f32, G0 [P,R] f32, G_mid [6,R,P,R] f32, G_last [R,P,OUT] f32, t
// Output: [B, OUT] f32
// ---------------------------------------------------------------------------
extern "C" void kernel_launch(void* const* d_in, const int* in_sizes, int n_in,
                              void* d_out, int out_size) {
    (void)in_sizes; (void)n_in; (void)out_size;
    const float* z     = (const float*)d_in[0];
    const float* G0    = (const float*)d_in[1];
    const float* Gmid  = (const float*)d_in[2];
    const float* Glast = (const float*)d_in[3];
    float* out = (float*)d_out;

    float *p_tg0, *p_resf, *p_sa, *p_sbm, *p_sbl, *p_stm, *p_stl;
    int8_t *p_qah, *p_qal, *p_qbhm, *p_qblm, *p_qbhl, *p_qbll;
    cudaGetSymbolAddress((void**)&p_tg0,  g_tanh_g0);
    cudaGetSymbolAddress((void**)&p_resf, g_resf);
    cudaGetSymbolAddress((void**)&p_sa,   g_sa);
    cudaGetSymbolAddress((void**)&p_qah,  g_qa_hi);
    cudaGetSymbolAddress((void**)&p_qal,  g_qa_lo);
    cudaGetSymbolAddress((void**)&p_qbhm, g_qb_hi_mid);
    cudaGetSymbolAddress((void**)&p_qblm, g_qb_lo_mid);
    cudaGetSymbolAddress((void**)&p_qbhl, g_qb_hi_last);
    cudaGetSymbolAddress((void**)&p_qbll, g_qb_lo_last);
    cudaGetSymbolAddress((void**)&p_sbm,  g_sb_mid);
    cudaGetSymbolAddress((void**)&p_sbl,  g_sb_last);
    cudaGetSymbolAddress((void**)&p_stm,  g_bstage_mid);
    cudaGetSymbolAddress((void**)&p_stl,  g_bstage_last);
    float *p_sbmaxm, *p_sbmaxl;
    cudaGetSymbolAddress((void**)&p_sbmaxm, g_sbmax_mid);
    cudaGetSymbolAddress((void**)&p_sbmaxl, g_sbmax_last);

    const int SMEM_IMMA = 4 * (2 * 128 * 64 + 2 * 64 * 64);  // 98304
    cudaFuncSetAttribute((const void*)tt_imma_kernel,
                         cudaFuncAttributeMaxDynamicSharedMemorySize, SMEM_IMMA);

    // --- precompute ---
    tanh_small_kernel<<<(P_SZ * R_SZ + 255) / 256, 256>>>(G0, p_tg0, P_SZ * R_SZ);
    zero_scales_kernel<<<(NMID * P_SZ * R_SZ + 255) / 256, 256>>>();
    btrans_pass1_kernel<<<dim3(R_SZ / 32, R_SZ / 32, NMID * P_SZ), dim3(32, 8)>>>(
        Gmid, p_stm, p_sbmaxm, R_SZ, (size_t)R_SZ * P_SZ * R_SZ, (size_t)R_SZ * KTOT);
    btrans_pass1_kernel<<<dim3(R_SZ / 32, OUT_SZ / 32, P_SZ), dim3(32, 8)>>>(
        Glast, p_stl, p_sbmaxl, OUT_SZ, 0, 0);
    {
        long totM = (long)NMID * R_SZ * KTOT;
        long totL = (long)OUT_SZ * KTOT;
        btrans_pass2_kernel<<<(unsigned)((totM + 255) / 256), 256>>>(
            p_stm, p_sbmaxm, p_qbhm, p_qblm, p_sbm, R_SZ, totM);
        btrans_pass2_kernel<<<(unsigned)((totL + 255) / 256), 256>>>(
            p_stl, p_sbmaxl, p_qbhl, p_qbll, p_sbl, OUT_SZ, totL);
    }

    // --- first core + quantize ---
    first_core_kernel<<<B_SZ, R_SZ>>>(z, p_resf);
    quant_res_kernel<<<B_SZ, R_SZ>>>(p_resf, p_qah, p_qal, p_sa);

    // --- six middle cores (int8 IMMA) ---
    for (int i = 0; i < NMID; i++) {
        tt_imma_kernel<<<dim3(R_SZ / 64, B_SZ / 128), 512, SMEM_IMMA>>>(
            p_qah, p_qal,
            p_qbhm + (size_t)i * R_SZ * KTOT, p_qblm + (size_t)i * R_SZ * KTOT,
            p_sa, p_sbm + i * P_SZ * R_SZ,
            z, i + 1, p_resf, R_SZ);
        quant_res_kernel<<<B_SZ, R_SZ>>>(p_resf, p_qah, p_qal, p_sa);
    }

    // --- last core -> d_out [B, OUT] ---
    tt_imma_kernel<<<dim3(1, B_SZ / 128), 512, SMEM_IMMA>>>(
        p_qah, p_qal, p_qbhl, p_qbll, p_sa, p_sbl,
        z, D_SZ - 1, out, OUT_SZ);
}

// round 10
// speedup vs baseline: 4.0415x; 4.0415x over previous
#include <cuda_runtime.h>
#include <cuda_fp16.h>
#include <cstdint>
#include <cstddef>

// ---------------------------------------------------------------------------
// Problem constants
// ---------------------------------------------------------------------------
#define B_SZ   8192
#define D_SZ   8
#define P_SZ   10
#define R_SZ   512
#define OUT_SZ 64
#define NMID   6
#define KTOT   (P_SZ * R_SZ)   // 5120
#define KC     32              // K per pipeline chunk
#define RCH    (R_SZ / KC)     // 16 chunks per j
#define NCH    (KTOT / KC)     // 160

// ---------------------------------------------------------------------------
// Device-global scratch
// ---------------------------------------------------------------------------
__device__ float  g_tanh_g0[P_SZ * R_SZ];
__device__ float  g_resf[(size_t)B_SZ * R_SZ];    // f32 master res between layers
__device__ __half g_qa_hi[(size_t)B_SZ * R_SZ];   // fp16 hi of res/s
__device__ __half g_qa_lo[(size_t)B_SZ * R_SZ];   // fp16 lo of res/s
__device__ float  g_sa[B_SZ];                     // per-row scale
// B operands: tanh'd, transposed to [n][k=j*512+r], SINGLE fp16 (|tanh|<=0.1)
__device__ __half g_b_mid[(size_t)NMID * R_SZ * KTOT];
__device__ __half g_b_last[(size_t)OUT_SZ * KTOT];

// ---------------------------------------------------------------------------
// PTX helpers (sm_80-era: cp.async, ldmatrix, mma.sync — NO tcgen05)
// ---------------------------------------------------------------------------
__device__ __forceinline__ uint32_t smem_u32(const void* p) {
    uint32_t a;
    asm("{ .reg .u64 t; cvta.to.shared.u64 t, %1; cvt.u32.u64 %0, t; }" : "=r"(a) : "l"(p));
    return a;
}
#define CP_ASYNC16(dst, src) \
    asm volatile("cp.async.cg.shared.global [%0], [%1], 16;" :: "r"(dst), "l"(src) : "memory")
#define CP_COMMIT() asm volatile("cp.async.commit_group;" ::: "memory")
#define CP_WAIT2()  asm volatile("cp.async.wait_group 2;" ::: "memory")

#define LDSM4(r0, r1, r2, r3, addr) \
    asm volatile("ldmatrix.sync.aligned.m8n8.x4.shared.b16 {%0,%1,%2,%3}, [%4];" \
                 : "=r"(r0), "=r"(r1), "=r"(r2), "=r"(r3) : "r"(addr))

#define MMA_F16(d, a, b) \
    asm volatile("mma.sync.aligned.m16n8k16.row.col.f32.f16.f16.f32 " \
                 "{%0,%1,%2,%3}, {%4,%5,%6,%7}, {%8,%9}, {%0,%1,%2,%3};" \
                 : "+f"((d)[0]), "+f"((d)[1]), "+f"((d)[2]), "+f"((d)[3]) \
                 : "r"((a)[0]), "r"((a)[1]), "r"((a)[2]), "r"((a)[3]), \
                   "r"((b)[0]), "r"((b)[1]))

// 64B-row XOR swizzle: conflict-free across all 8-row ldmatrix phases.
__device__ __forceinline__ uint32_t sw64(uint32_t row, uint32_t c16) {
    return row * 64u + ((c16 ^ ((row >> 1) & 3u)) << 4);
}

// ---------------------------------------------------------------------------
// Precompute: tanh + transpose -> single fp16
//   G [R, P, N] (n contiguous) -> B [n][j*512 + r] (k contiguous)
// ---------------------------------------------------------------------------
__global__ void trans_f16_kernel(const float* __restrict__ G,
                                 __half* __restrict__ bo,
                                 int N, size_t gStride, size_t oStride) {
    __shared__ float t[32][33];
    int layer = blockIdx.z / P_SZ;
    int j     = blockIdx.z % P_SZ;
    const float* Gp = G + (size_t)layer * gStride;
    __half* bop = bo + (size_t)layer * oStride;
    int rt = blockIdx.x * 32, nt = blockIdx.y * 32;
    int tx = threadIdx.x, ty = threadIdx.y;   // block (32, 8)
#pragma unroll
    for (int yy = ty; yy < 32; yy += 8)
        t[yy][tx] = tanhf(Gp[((size_t)(rt + yy) * P_SZ + j) * N + nt + tx]);
    __syncthreads();
#pragma unroll
    for (int yy = ty; yy < 32; yy += 8) {
        int n = nt + yy, r = rt + tx;
        bop[(size_t)n * KTOT + (size_t)j * R_SZ + r] = __float2half_rn(t[tx][yy]);
    }
}

__global__ void tanh_small_kernel(const float* __restrict__ src,
                                  float* __restrict__ dst, int n) {
    int i = blockIdx.x * blockDim.x + threadIdx.x;
    if (i < n) dst[i] = tanhf(src[i]);
}

// First core -> f32 res
__global__ void first_core_kernel(const float* __restrict__ z,
                                  float* __restrict__ resf) {
    int b = blockIdx.x;
    int r = threadIdx.x;
    float zv = z[b * D_SZ + 0];
    float ph = 1.f, acc = 0.f;
#pragma unroll
    for (int j = 0; j < P_SZ; j++) {
        acc += g_tanh_g0[j * R_SZ + r] * ph;
        ph *= zv;
    }
    resf[(size_t)b * R_SZ + r] = acc;
}

// Per-row quantize: s = rowmax |x|; A_hi = fp16(x/s), A_lo = fp16(x/s - hi)
__global__ void quant_res_kernel(const float* __restrict__ resf,
                                 __half* __restrict__ qh, __half* __restrict__ ql,
                                 float* __restrict__ sa) {
    __shared__ float wmax[16];
    int b = blockIdx.x, tid = threadIdx.x;   // 512 threads
    float x = resf[(size_t)b * R_SZ + tid];
    float a = fabsf(x);
#pragma unroll
    for (int o = 16; o; o >>= 1) a = fmaxf(a, __shfl_xor_sync(0xffffffffu, a, o));
    if ((tid & 31) == 0) wmax[tid >> 5] = a;
    __syncthreads();
    if (tid < 32) {
        float m = (tid < 16) ? wmax[tid] : 0.f;
#pragma unroll
        for (int o = 8; o; o >>= 1) m = fmaxf(m, __shfl_xor_sync(0xffffffffu, m, o));
        if (tid == 0) wmax[0] = m;
    }
    __syncthreads();
    float s = fmaxf(wmax[0], 1e-30f);
    float inv = 1.0f / s;
    float q = x * inv;
    __half h = __float2half_rn(q);
    qh[(size_t)b * R_SZ + tid] = h;
    ql[(size_t)b * R_SZ + tid] = __float2half_rn(q - __half2float(h));
    if (tid == 0) sa[b] = s;
}

// ---------------------------------------------------------------------------
// HMMA fp16 2-pass GEMM with Horner phi folding + per-row scale:
//   out[m,n] = sA[m] * sum_{j desc} ( acc*z_m + sum_r (Ah+Al)[m,r] B_j[r,n] )
// THREADS threads; warp grid (BM/WM) x (BN/WN); 4-stage cp.async pipeline.
// Epilogue writes f32 (next layer's quantizer reads it; last layer -> d_out).
// ---------------------------------------------------------------------------
template<int BM, int BN, int WM, int WN, int THREADS>
__global__ void __launch_bounds__(THREADS, 1)
tt_mma_kernel(const __half* __restrict__ Ahi,
              const __half* __restrict__ Alo,
              const __half* __restrict__ Bop,
              const float* __restrict__ sa,
              const float* __restrict__ z, int zcol,
              float* __restrict__ outF, int Ntotal) {
    constexpr int MT = WM / 16, NT = WN / 8;
    constexpr int A_T = BM * 64;               // one A array per stage, bytes
    constexpr int B_T = BN * 64;
    constexpr int STAGE = 2 * A_T + B_T;
    constexpr int NSTAGE = 4;

    extern __shared__ __align__(16) char sm[];
    const uint32_t base = smem_u32(sm);

    const int tid = threadIdx.x, lane = tid & 31, wid = tid >> 5;
    const int m0 = blockIdx.y * BM, n0 = blockIdx.x * BN;
    constexpr int NWC = BN / WN;
    const int wm0 = (wid / NWC) * WM;
    const int wn0 = (wid % NWC) * WN;

    // per-lane z + scale (rows r, r+8 per mt quad)
    float zA[MT], zB[MT], sA[MT], sB[MT];
#pragma unroll
    for (int mt = 0; mt < MT; mt++) {
        int rA = m0 + wm0 + mt * 16 + (lane >> 2);
        zA[mt] = z[(size_t)rA * D_SZ + zcol];
        zB[mt] = z[(size_t)(rA + 8) * D_SZ + zcol];
        sA[mt] = sa[rA];
        sB[mt] = sa[rA + 8];
    }

    float acc[MT][NT][4];
#pragma unroll
    for (int mt = 0; mt < MT; mt++)
#pragma unroll
        for (int nt = 0; nt < NT; nt++)
#pragma unroll
            for (int q = 0; q < 4; q++) acc[mt][nt][q] = 0.f;

    auto produce = [&](int cc) {
        const int s = cc & (NSTAGE - 1);
        const int j = (P_SZ - 1) - cc / RCH;       // descending j
        const int rr = cc & (RCH - 1);
        const int roffA = rr * KC;
        const int koffB = j * R_SZ + rr * KC;
        const uint32_t aH = base + s * STAGE;
        const uint32_t aL = aH + A_T;
        const uint32_t bS = aH + 2 * A_T;
#pragma unroll
        for (int i = 0; i < (BM * 4) / THREADS; i++) {
            const int idx = tid + i * THREADS;
            const int row = idx >> 2, c16 = idx & 3;
            const uint32_t off = sw64(row, c16);
            const size_t go = (size_t)(m0 + row) * R_SZ + roffA + c16 * 8;
            CP_ASYNC16(aH + off, Ahi + go);
            CP_ASYNC16(aL + off, Alo + go);
        }
#pragma unroll
        for (int i = 0; i < (BN * 4) / THREADS; i++) {
            const int idx = tid + i * THREADS;
            const int row = idx >> 2, c16 = idx & 3;
            const uint32_t off = sw64(row, c16);
            const size_t go = (size_t)(n0 + row) * KTOT + koffB + c16 * 8;
            CP_ASYNC16(bS + off, Bop + go);
        }
        CP_COMMIT();
    };

    auto mma_chunk = [&](int s) {
        const uint32_t aH = base + s * STAGE;
        const uint32_t aL = aH + A_T;
        const uint32_t bS = aH + 2 * A_T;
#pragma unroll
        for (int ks = 0; ks < 2; ks++) {
            uint32_t b[NT][2];
#pragma unroll
            for (int n2 = 0; n2 < NT / 2; n2++) {
                const uint32_t rowb = wn0 + n2 * 16 + ((lane >> 4) << 3) + (lane & 7);
                const uint32_t c16b = ((lane >> 3) & 1) + 2 * ks;
                LDSM4(b[2 * n2][0], b[2 * n2][1], b[2 * n2 + 1][0], b[2 * n2 + 1][1],
                      bS + sw64(rowb, c16b));
            }
            uint32_t a[MT][4];
#pragma unroll
            for (int mt = 0; mt < MT; mt++) {
                const uint32_t rowa = wm0 + mt * 16 + (lane & 15);
                LDSM4(a[mt][0], a[mt][1], a[mt][2], a[mt][3],
                      aH + sw64(rowa, (lane >> 4) + 2 * ks));
            }
#pragma unroll
            for (int mt = 0; mt < MT; mt++)
#pragma unroll
                for (int nt = 0; nt < NT; nt++) MMA_F16(acc[mt][nt], a[mt], b[nt]);
#pragma unroll
            for (int mt = 0; mt < MT; mt++) {
                const uint32_t rowa = wm0 + mt * 16 + (lane & 15);
                LDSM4(a[mt][0], a[mt][1], a[mt][2], a[mt][3],
                      aL + sw64(rowa, (lane >> 4) + 2 * ks));
            }
#pragma unroll
            for (int mt = 0; mt < MT; mt++)
#pragma unroll
                for (int nt = 0; nt < NT; nt++) MMA_F16(acc[mt][nt], a[mt], b[nt]);
        }
    };

    // prologue: 3 stages in flight
    produce(0); produce(1); produce(2);

    for (int c = 0; c < NCH; c++) {
        CP_WAIT2();
        __syncthreads();
        if (c + 3 < NCH) produce(c + 3); else CP_COMMIT();
        if (c && (c & (RCH - 1)) == 0) {
            // Horner: entering next-lower j — scale accumulators by z
#pragma unroll
            for (int mt = 0; mt < MT; mt++)
#pragma unroll
                for (int nt = 0; nt < NT; nt++) {
                    acc[mt][nt][0] *= zA[mt]; acc[mt][nt][1] *= zA[mt];
                    acc[mt][nt][2] *= zB[mt]; acc[mt][nt][3] *= zB[mt];
                }
        }
        mma_chunk(c & (NSTAGE - 1));
    }

    // epilogue: apply per-row scale, write f32
#pragma unroll
    for (int mt = 0; mt < MT; mt++) {
        const int row0 = m0 + wm0 + mt * 16 + (lane >> 2);
#pragma unroll
        for (int nt = 0; nt < NT; nt++) {
            const int col = n0 + wn0 + nt * 8 + (lane & 3) * 2;
            *reinterpret_cast<float2*>(&outF[(size_t)row0 * Ntotal + col]) =
                make_float2(acc[mt][nt][0] * sA[mt], acc[mt][nt][1] * sA[mt]);
            *reinterpret_cast<float2*>(&outF[(size_t)(row0 + 8) * Ntotal + col]) =
                make_float2(acc[mt][nt][2] * sB[mt], acc[mt][nt][3] * sB[mt]);
        }
    }
}

// ---------------------------------------------------------------------------
// Launch (graph-capturable, allocation-free)
// Inputs: z [B,D] f32, G0 [P,R] f32, G_mid [6,R,P,R] f32, G_last [R,P,OUT] f32, t
// Output: [B, OUT] f32
// ---------------------------------------------------------------------------
extern "C" void kernel_launch(void* const* d_in, const int* in_sizes, int n_in,
                              void* d_out, int out_size) {
    (void)in_sizes; (void)n_in; (void)out_size;
    const float* z     = (const float*)d_in[0];
    const float* G0    = (const float*)d_in[1];
    const float* Gmid  = (const float*)d_in[2];
    const float* Glast = (const float*)d_in[3];
    float* out = (float*)d_out;

    float *p_tg0, *p_resf, *p_sa;
    __half *p_qah, *p_qal, *p_bm, *p_bl;
    cudaGetSymbolAddress((void**)&p_tg0,  g_tanh_g0);
    cudaGetSymbolAddress((void**)&p_resf, g_resf);
    cudaGetSymbolAddress((void**)&p_sa,   g_sa);
    cudaGetSymbolAddress((void**)&p_qah,  g_qa_hi);
    cudaGetSymbolAddress((void**)&p_qal,  g_qa_lo);
    cudaGetSymbolAddress((void**)&p_bm,   g_b_mid);
    cudaGetSymbolAddress((void**)&p_bl,   g_b_last);

    // dynamic smem: 4 stages x (2*BM + BN) * 64 bytes
    const int SMEM_MID  = 4 * (2 * 256 + 128) * 64;  // 163840
    const int SMEM_LAST = 4 * (2 * 64 + 64) * 64;    // 49152
    cudaFuncSetAttribute((const void*)tt_mma_kernel<256, 128, 64, 32, 512>,
                         cudaFuncAttributeMaxDynamicSharedMemorySize, SMEM_MID);
    cudaFuncSetAttribute((const void*)tt_mma_kernel<64, 64, 32, 16, 256>,
                         cudaFuncAttributeMaxDynamicSharedMemorySize, SMEM_LAST);

    // precompute
    tanh_small_kernel<<<(P_SZ * R_SZ + 255) / 256, 256>>>(G0, p_tg0, P_SZ * R_SZ);
    trans_f16_kernel<<<dim3(R_SZ / 32, R_SZ / 32, NMID * P_SZ), dim3(32, 8)>>>(
        Gmid, p_bm, R_SZ, (size_t)R_SZ * P_SZ * R_SZ, (size_t)R_SZ * KTOT);
    trans_f16_kernel<<<dim3(R_SZ / 32, OUT_SZ / 32, P_SZ), dim3(32, 8)>>>(
        Glast, p_bl, OUT_SZ, 0, 0);

    // first core -> f32 res -> quantize
    first_core_kernel<<<B_SZ, R_SZ>>>(z, p_resf);
    quant_res_kernel<<<B_SZ, R_SZ>>>(p_resf, p_qah, p_qal, p_sa);

    // six middle cores: GEMM (f32 out) + per-row quantize
    for (int i = 0; i < NMID; i++) {
        tt_mma_kernel<256, 128, 64, 32, 512>
            <<<dim3(R_SZ / 128, B_SZ / 256), 512, SMEM_MID>>>(
            p_qah, p_qal, p_bm + (size_t)i * R_SZ * KTOT, p_sa,
            z, i + 1, p_resf, R_SZ);
        quant_res_kernel<<<B_SZ, R_SZ>>>(p_resf, p_qah, p_qal, p_sa);
    }

    // last core -> d_out [B, OUT] f32
    tt_mma_kernel<64, 64, 32, 16, 256><<<dim3(1, B_SZ / 64), 256, SMEM_LAST>>>(
        p_qah, p_qal, p_bl, p_sa, z, D_SZ - 1, out, OUT_SZ);
}